// round 1
// baseline (speedup 1.0000x reference)
#include <cuda_runtime.h>
#include <cstdint>
#include <cstddef>

// ---------------------------------------------------------------------------
// NeuralDecisionTree fused kernel (fp32 SIMT, f32x2-packed FMA)
//
//   route = sigmoid(x @ Wr^T + br)            [B,63]
//   path  = tree product of route             [B,64]
//   h_l   = relu(x @ W1[l] + b1[l])           per leaf, [B,64]
//   out   = sum_l path[:,l] * (h_l @ W2[l] + b2[l])
//
// Restructured: out = (path-scaled h, concatenated over leaves) @ W2_flat
//               + path @ b2, fully fused per 128-row batch tile.
// ---------------------------------------------------------------------------

#define DEPTHT   6
#define LEAVES   64
#define NODES    63
#define DIN      128
#define HDIM     64
#define DOUT     10
#define BATCH    32768
#define TILE_B   128
#define NTHREADS 256

// shared memory layout (float offsets)
#define XT_STRIDE 132                          // padded to dodge bank conflicts
#define HS_STRIDE 68
#define RT_STRIDE 65
#define OFF_XT    0                                   // 128*132 = 16896
#define OFF_W1    (OFF_XT + DIN * XT_STRIDE)          // 2 * 8192 = 16384
#define OFF_PATH  (OFF_W1 + 2 * DIN * HDIM)           // 64*128   = 8192
#define OFF_HS    (OFF_PATH + LEAVES * TILE_B)        // 128*68   = 8704 (route overlay)
#define OFF_W2    (OFF_HS + TILE_B * HS_STRIDE)       // 2 * 640  = 1280
#define OFF_B2    (OFF_W2 + 2 * DOUT * HDIM)          // 2 * 16   = 32
#define SMEM_FLOATS (OFF_B2 + 32)                     // 51488 floats = 205952 B

// ---- f32x2 packed-FMA helpers ---------------------------------------------
__device__ __forceinline__ unsigned long long dup_f32x2(float v) {
    unsigned long long r;
    asm("mov.b64 %0, {%1, %1};" : "=l"(r) : "f"(v));
    return r;
}
__device__ __forceinline__ void fma_f32x2(unsigned long long& a,
                                          unsigned long long x,
                                          unsigned long long y) {
    asm("fma.rn.f32x2 %0, %1, %2, %0;" : "+l"(a) : "l"(x), "l"(y));
}
__device__ __forceinline__ float2 unpack_f32x2(unsigned long long v) {
    float lo, hi;
    asm("mov.b64 {%0, %1}, %2;" : "=f"(lo), "=f"(hi) : "l"(v));
    return make_float2(lo, hi);
}

// ---- cp.async helper -------------------------------------------------------
__device__ __forceinline__ void cp_async16(uint32_t saddr, const void* g) {
    asm volatile("cp.async.cg.shared.global [%0], [%1], 16;"
                 :: "r"(saddr), "l"(g) : "memory");
}

__device__ __forceinline__ void issue_w1(const float* __restrict__ W1, int leaf,
                                         float* dst) {
    const char* g = (const char*)(W1 + (size_t)leaf * DIN * HDIM);
    uint32_t s = (uint32_t)__cvta_generic_to_shared(dst);
#pragma unroll
    for (int k = 0; k < 8; k++) {
        int c = threadIdx.x + k * NTHREADS;   // 2048 chunks x 16B = 32 KB
        cp_async16(s + c * 16, g + c * 16);
    }
}

extern __shared__ float sm[];

__global__ void __launch_bounds__(NTHREADS, 1)
ndt_kernel(const float* __restrict__ x,  const float* __restrict__ Wr,
           const float* __restrict__ br, const float* __restrict__ W1,
           const float* __restrict__ b1, const float* __restrict__ W2,
           const float* __restrict__ b2, float* __restrict__ out)
{
    const int tid   = threadIdx.x;
    const int gbase = blockIdx.x * TILE_B;

    float* XT     = sm + OFF_XT;    // x transposed: XT[d][i], stride 132
    float* W1S    = sm + OFF_W1;    // double-buffered W1[l]: [128][64]
    float* PATHT  = sm + OFF_PATH;  // path transposed: PATHT[l][i]
    float* HS     = sm + OFF_HS;    // scaled relu(h): HS[i][j], stride 68
    float* ROUTES = sm + OFF_HS;    // phase-0 overlay: ROUTES[i][n], stride 65
    float* W2T    = sm + OFF_W2;    // double-buffered W2[l]^T: [10][64]
    float* B2S    = sm + OFF_B2;    // double-buffered b2[l]: [16]

    // ---------------- phase 0: load x (transposed) + Wr into smem ----------
    {
        const float4* xg = (const float4*)(x + (size_t)gbase * DIN);
        for (int f = tid; f < TILE_B * (DIN / 4); f += NTHREADS) {
            int i  = f >> 5;
            int dq = f & 31;
            float4 v = __ldg(&xg[i * 32 + dq]);
            int d = dq * 4;
            XT[(d + 0) * XT_STRIDE + i] = v.x;
            XT[(d + 1) * XT_STRIDE + i] = v.y;
            XT[(d + 2) * XT_STRIDE + i] = v.z;
            XT[(d + 3) * XT_STRIDE + i] = v.w;
        }
        const float4* wrg = (const float4*)Wr;
        for (int f = tid; f < NODES * (DIN / 4); f += NTHREADS)
            ((float4*)W1S)[f] = __ldg(&wrg[f]);      // Wr staged in W1S buf0
    }
    __syncthreads();

    // ---------------- route: sigmoid(x @ Wr^T + br) -------------------------
    // 63 nodes x 32 row-quads; warp shares node n (smem broadcast on Wr row).
    for (int t = tid; t < NODES * 32; t += NTHREADS) {
        int n  = t >> 5;
        int i0 = (t & 31) * 4;
        float4 acc = make_float4(0.f, 0.f, 0.f, 0.f);
        const float* wrow = W1S + n * DIN;
#pragma unroll 8
        for (int d = 0; d < DIN; d++) {
            float  w  = wrow[d];
            float4 xv = *(const float4*)&XT[d * XT_STRIDE + i0];
            acc.x = fmaf(xv.x, w, acc.x);
            acc.y = fmaf(xv.y, w, acc.y);
            acc.z = fmaf(xv.z, w, acc.z);
            acc.w = fmaf(xv.w, w, acc.w);
        }
        float bn = __ldg(&br[n]);
        ROUTES[(i0 + 0) * RT_STRIDE + n] = 1.f / (1.f + __expf(-(acc.x + bn)));
        ROUTES[(i0 + 1) * RT_STRIDE + n] = 1.f / (1.f + __expf(-(acc.y + bn)));
        ROUTES[(i0 + 2) * RT_STRIDE + n] = 1.f / (1.f + __expf(-(acc.z + bn)));
        ROUTES[(i0 + 3) * RT_STRIDE + n] = 1.f / (1.f + __expf(-(acc.w + bn)));
    }
    __syncthreads();   // route done; W1S (Wr staging) now free

    // ---------------- kick off pipeline for leaf 0 --------------------------
    issue_w1(W1, 0, W1S);                                   // -> buffer 0
    asm volatile("cp.async.commit_group;" ::: "memory");
    // stage W2[0]^T + b2[0] into buffer 0 (plain ld/st; consumed after syncs)
    for (int idx = tid; idx < DOUT * HDIM; idx += NTHREADS) {
        int o = idx >> 6, j = idx & 63;
        W2T[o * HDIM + j] = __ldg(&W2[(size_t)j * DOUT + o]);
    }
    if (tid < DOUT) B2S[tid] = __ldg(&b2[tid]);

    // ---------------- path: product of sigmoids along tree ------------------
    if (tid < TILE_B) {
        const int i = tid;
        for (int l = 0; l < LEAVES; l++) {
            float p = 1.f;
#pragma unroll
            for (int k = 0; k < DEPTHT; k++) {
                int node = (1 << k) - 1 + (l >> (DEPTHT - k));
                int bit  = (l >> (DEPTHT - 1 - k)) & 1;
                float dv = ROUTES[i * RT_STRIDE + node];
                p *= bit ? (1.f - dv) : dv;
            }
            PATHT[l * TILE_B + i] = p;
        }
    }

    // ---------------- main leaf loop ----------------------------------------
    const int r0 = (tid >> 4) * 8;        // stage1: 8 rows
    const int j0 = (tid & 15) * 4;        // stage1: 4 cols
    const int i2 = tid >> 1;              // stage2: row
    const int o0 = (tid & 1) * 5;         // stage2: 5 outputs

    unsigned long long oacc[5] = {0ull, 0ull, 0ull, 0ull, 0ull};
    float bterm[5] = {0.f, 0.f, 0.f, 0.f, 0.f};

    for (int l = 0; l < LEAVES; l++) {
        const int buf = l & 1;

        if (l + 1 < LEAVES) {
            issue_w1(W1, l + 1, W1S + (buf ^ 1) * DIN * HDIM);
            asm volatile("cp.async.commit_group;" ::: "memory");
            asm volatile("cp.async.wait_group 1;" ::: "memory");
        } else {
            asm volatile("cp.async.wait_group 0;" ::: "memory");
        }
        __syncthreads();   // sync_A: W1[l] visible; HS + W2T[buf^1] free

        // prefetch W2[l+1]^T / b2[l+1] into registers (STS after the GEMM)
        float w2pre[3] = {0.f, 0.f, 0.f};
        float b2pre = 0.f;
        if (l + 1 < LEAVES) {
            const float* w2g = W2 + (size_t)(l + 1) * HDIM * DOUT;
#pragma unroll
            for (int k = 0; k < 3; k++) {
                int idx = tid + k * NTHREADS;
                if (idx < DOUT * HDIM) {
                    int o = idx >> 6, j = idx & 63;
                    w2pre[k] = __ldg(&w2g[j * DOUT + o]);
                }
            }
            if (tid < DOUT) b2pre = __ldg(&b2[(l + 1) * DOUT + tid]);
        }

        // ---- stage 1: h = x_tile @ W1[l]  (8x4 microtile, f32x2 packed) ----
        unsigned long long acc[4][4];
#pragma unroll
        for (int p = 0; p < 4; p++)
#pragma unroll
            for (int j = 0; j < 4; j++) acc[p][j] = 0ull;

        const float* w1p = W1S + buf * DIN * HDIM;
#pragma unroll 8
        for (int d = 0; d < DIN; d++) {
            ulonglong2 a01 = *(const ulonglong2*)&XT[d * XT_STRIDE + r0];
            ulonglong2 a23 = *(const ulonglong2*)&XT[d * XT_STRIDE + r0 + 4];
            float4 bv = *(const float4*)&w1p[d * HDIM + j0];
            unsigned long long ap[4] = {a01.x, a01.y, a23.x, a23.y};
            unsigned long long bd[4] = {dup_f32x2(bv.x), dup_f32x2(bv.y),
                                        dup_f32x2(bv.z), dup_f32x2(bv.w)};
#pragma unroll
            for (int p = 0; p < 4; p++)
#pragma unroll
                for (int j = 0; j < 4; j++)
                    fma_f32x2(acc[p][j], ap[p], bd[j]);
        }

        // store W2/b2 prefetch into the other buffer
        if (l + 1 < LEAVES) {
            float* w2d = W2T + (buf ^ 1) * DOUT * HDIM;
#pragma unroll
            for (int k = 0; k < 3; k++) {
                int idx = tid + k * NTHREADS;
                if (idx < DOUT * HDIM) {
                    int o = idx >> 6, j = idx & 63;
                    w2d[o * HDIM + j] = w2pre[k];
                }
            }
            if (tid < DOUT) B2S[(buf ^ 1) * 16 + tid] = b2pre;
        }

        // ---- epilogue: bias + relu + path-scale -> HS ----------------------
        {
            float4 b1v = __ldg((const float4*)&b1[l * HDIM + j0]);
            float bb[4] = {b1v.x, b1v.y, b1v.z, b1v.w};
            float4 pA = *(const float4*)&PATHT[l * TILE_B + r0];
            float4 pB = *(const float4*)&PATHT[l * TILE_B + r0 + 4];
            float pr[8] = {pA.x, pA.y, pA.z, pA.w, pB.x, pB.y, pB.z, pB.w};
#pragma unroll
            for (int p = 0; p < 4; p++) {
                float lo[4], hi[4];
#pragma unroll
                for (int j = 0; j < 4; j++) {
                    float2 v = unpack_f32x2(acc[p][j]);
                    lo[j] = fmaxf(v.x + bb[j], 0.f) * pr[2 * p];
                    hi[j] = fmaxf(v.y + bb[j], 0.f) * pr[2 * p + 1];
                }
                *(float4*)&HS[(r0 + 2 * p)     * HS_STRIDE + j0] =
                    make_float4(lo[0], lo[1], lo[2], lo[3]);
                *(float4*)&HS[(r0 + 2 * p + 1) * HS_STRIDE + j0] =
                    make_float4(hi[0], hi[1], hi[2], hi[3]);
            }
        }
        __syncthreads();   // sync_B: HS + W2T[buf] ready for stage 2

        // ---- stage 2: out += HS_row @ W2[l]^T + path*b2 --------------------
        {
            const float* hrow = &HS[i2 * HS_STRIDE];
            const float* w2p  = W2T + buf * DOUT * HDIM;
#pragma unroll
            for (int jq = 0; jq < 16; jq++) {
                ulonglong2 h2 = *(const ulonglong2*)&hrow[jq * 4];
#pragma unroll
                for (int o = 0; o < 5; o++) {
                    ulonglong2 w2v =
                        *(const ulonglong2*)&w2p[(o0 + o) * HDIM + jq * 4];
                    fma_f32x2(oacc[o], h2.x, w2v.x);
                    fma_f32x2(oacc[o], h2.y, w2v.y);
                }
            }
            float s = PATHT[l * TILE_B + i2];
#pragma unroll
            for (int o = 0; o < 5; o++)
                bterm[o] = fmaf(s, B2S[buf * 16 + o0 + o], bterm[o]);
        }
    }

    // ---------------- write output ------------------------------------------
    float* op = out + (size_t)(gbase + i2) * DOUT + o0;
#pragma unroll
    for (int o = 0; o < 5; o++) {
        float2 v = unpack_f32x2(oacc[o]);
        op[o] = v.x + v.y + bterm[o];
    }
}

// ---------------------------------------------------------------------------
extern "C" void kernel_launch(void* const* d_in, const int* in_sizes, int n_in,
                              void* d_out, int out_size) {
    const float* x  = (const float*)d_in[0];
    const float* Wr = (const float*)d_in[1];
    const float* br = (const float*)d_in[2];
    const float* W1 = (const float*)d_in[3];
    const float* b1 = (const float*)d_in[4];
    const float* W2 = (const float*)d_in[5];
    const float* b2 = (const float*)d_in[6];
    float* out = (float*)d_out;

    const size_t smem = SMEM_FLOATS * sizeof(float);   // ~201 KB
    cudaFuncSetAttribute(ndt_kernel,
                         cudaFuncAttributeMaxDynamicSharedMemorySize,
                         (int)smem);
    ndt_kernel<<<BATCH / TILE_B, NTHREADS, smem>>>(x, Wr, br, W1, b1, W2, b2,
                                                   out);
}